// round 7
// baseline (speedup 1.0000x reference)
#include <cuda_runtime.h>
#include <math.h>

#define N_NODES 100000
#define HID 128
#define NTYPES 4
#define BM 64
#define GEMM_THREADS 256

// ---------------- scratch (__device__ globals; referenced ONLY in device code) --
__device__ float g_res[N_NODES * HID];   // adapt output
__device__ float g_xw[N_NODES * HID];    // x @ W scratch (reused both layers)
__device__ float g_h1[N_NODES * HID];    // layer-1 output
__device__ float g_dinv[N_NODES];
__device__ int   g_deg[N_NODES];
__device__ int   g_cnt[NTYPES];
__device__ int   g_off[NTYPES];
__device__ int   g_cur[NTYPES];
__device__ int   g_perm[N_NODES];

// ---------------- small prep kernels -------------------------------------------
__global__ void k_init(int n) {
    int i = blockIdx.x * blockDim.x + threadIdx.x;
    if (i < n) g_deg[i] = 1;                 // self loop
    if (i < NTYPES) { g_cnt[i] = 0; g_cur[i] = 0; }
}

__global__ void k_count_types(const int* __restrict__ ntype, int n) {
    int i = blockIdx.x * blockDim.x + threadIdx.x;
    if (i < n) {
        int t = ntype[i];
        t = (t < 0) ? 0 : (t >= NTYPES ? NTYPES - 1 : t);
        atomicAdd(&g_cnt[t], 1);
    }
}

__global__ void k_deg(const int* __restrict__ dst, int e, int n) {
    int i = blockIdx.x * blockDim.x + threadIdx.x;
    if (i < e) {
        int d = dst[i];
        if (d >= 0 && d < n) atomicAdd(&g_deg[d], 1);
    }
}

__global__ void k_offsets() {
    int acc = 0;
    for (int t = 0; t < NTYPES; t++) { g_off[t] = acc; g_cur[t] = acc; acc += g_cnt[t]; }
}

__global__ void k_perm(const int* __restrict__ ntype, int n) {
    int i = blockIdx.x * blockDim.x + threadIdx.x;
    if (i < n) {
        int t = ntype[i];
        t = (t < 0) ? 0 : (t >= NTYPES ? NTYPES - 1 : t);
        int p = atomicAdd(&g_cur[t], 1);
        if (p >= 0 && p < n) g_perm[p] = i;
    }
}

__global__ void k_dinv(int n) {
    int i = blockIdx.x * blockDim.x + threadIdx.x;
    if (i < n) g_dinv[i] = rsqrtf((float)g_deg[i]);
}

// ---------------- adapt: per-type gather-GEMM + bias + tanh --------------------
// writes g_res directly (device-side symbol access). 48KB static smem.
__global__ void __launch_bounds__(GEMM_THREADS)
k_adapt(const float* __restrict__ X,
        const float* __restrict__ aW,
        const float* __restrict__ ab) {
    __shared__ float sW[64 * HID];   // 32KB
    __shared__ float sA[BM * 64];    // 16KB

    int t = blockIdx.y;
    int count = g_cnt[t];
    int row0 = blockIdx.x * BM;
    if (row0 >= count) return;
    int offt = g_off[t];
    int tid = threadIdx.x;
    int tx = tid & 31, ty = tid >> 5;

    float4* sW4 = (float4*)sW;
    float4* sA4 = (float4*)sA;
    const float4* X4 = (const float4*)X;

    float4 acc[8];
    #pragma unroll
    for (int i = 0; i < 8; i++) acc[i] = make_float4(0.f, 0.f, 0.f, 0.f);

    for (int p = 0; p < 2; p++) {
        const float4* W4 = (const float4*)(aW + ((size_t)t * HID + p * 64) * HID);
        for (int i = tid; i < 64 * 32; i += GEMM_THREADS) sW4[i] = W4[i];
        for (int i = tid; i < BM * 16; i += GEMM_THREADS) {
            int r = i >> 4;
            int idx = row0 + r;
            float4 v = make_float4(0.f, 0.f, 0.f, 0.f);
            if (idx < count) {
                int g = g_perm[offt + idx];
                v = X4[(size_t)g * 32 + p * 16 + (i & 15)];
            }
            sA4[i] = v;
        }
        __syncthreads();

        #pragma unroll 4
        for (int k = 0; k < 64; k += 4) {
            float4 w0 = sW4[(k + 0) * 32 + tx];
            float4 w1 = sW4[(k + 1) * 32 + tx];
            float4 w2 = sW4[(k + 2) * 32 + tx];
            float4 w3 = sW4[(k + 3) * 32 + tx];
            #pragma unroll
            for (int i = 0; i < 8; i++) {
                float4 a = sA4[(ty * 8 + i) * 16 + (k >> 2)];
                acc[i].x += a.x * w0.x; acc[i].y += a.x * w0.y; acc[i].z += a.x * w0.z; acc[i].w += a.x * w0.w;
                acc[i].x += a.y * w1.x; acc[i].y += a.y * w1.y; acc[i].z += a.y * w1.z; acc[i].w += a.y * w1.w;
                acc[i].x += a.z * w2.x; acc[i].y += a.z * w2.y; acc[i].z += a.z * w2.z; acc[i].w += a.z * w2.w;
                acc[i].x += a.w * w3.x; acc[i].y += a.w * w3.y; acc[i].z += a.w * w3.z; acc[i].w += a.w * w3.w;
            }
        }
        __syncthreads();
    }

    float4 b = ((const float4*)(ab + t * HID))[tx];
    #pragma unroll
    for (int i = 0; i < 8; i++) {
        int idx = row0 + ty * 8 + i;
        if (idx < count) {
            int g = g_perm[offt + idx];
            float4 v;
            v.x = tanhf(acc[i].x + b.x);
            v.y = tanhf(acc[i].y + b.y);
            v.z = tanhf(acc[i].z + b.z);
            v.w = tanhf(acc[i].w + b.w);
            ((float4*)g_res)[(size_t)g * 32 + tx] = v;
        }
    }
}

// ---------------- dense 128-col GEMM with fused self-loop epilogue --------------
// which = 0: A = g_res (layer 1), out = g_h1.   which = 1: A = g_h1, out = dout.
// Writes BOTH:  g_xw[r] = acc[r]  (raw, needed by k_scatter)
//          and  out[r]  = acc[r] * dinv[r]^2 + bias   (self-loop init)
__global__ void __launch_bounds__(GEMM_THREADS)
k_gemm(int which, const float* __restrict__ W, const float* __restrict__ bias,
       float* dout, int nrows) {
    __shared__ float sW[64 * HID];   // 32KB
    __shared__ float sA[BM * 64];    // 16KB

    const float4* A4 = which ? (const float4*)g_h1 : (const float4*)g_res;
    float4* out4 = which ? (float4*)dout : (float4*)g_h1;

    int tid = threadIdx.x;
    int row0 = blockIdx.x * BM;
    int tx = tid & 31, ty = tid >> 5;

    float4* sW4 = (float4*)sW;
    float4* sA4 = (float4*)sA;

    float4 acc[8];
    #pragma unroll
    for (int i = 0; i < 8; i++) acc[i] = make_float4(0.f, 0.f, 0.f, 0.f);

    for (int p = 0; p < 2; p++) {
        const float4* W4 = (const float4*)(W + (size_t)p * 64 * HID);
        for (int i = tid; i < 64 * 32; i += GEMM_THREADS) sW4[i] = W4[i];
        for (int i = tid; i < BM * 16; i += GEMM_THREADS) {
            int r = i >> 4;
            int gr = row0 + r;
            sA4[i] = (gr < nrows) ? A4[(size_t)gr * 32 + p * 16 + (i & 15)]
                                  : make_float4(0.f, 0.f, 0.f, 0.f);
        }
        __syncthreads();

        #pragma unroll 4
        for (int k = 0; k < 64; k += 4) {
            float4 w0 = sW4[(k + 0) * 32 + tx];
            float4 w1 = sW4[(k + 1) * 32 + tx];
            float4 w2 = sW4[(k + 2) * 32 + tx];
            float4 w3 = sW4[(k + 3) * 32 + tx];
            #pragma unroll
            for (int i = 0; i < 8; i++) {
                float4 a = sA4[(ty * 8 + i) * 16 + (k >> 2)];
                acc[i].x += a.x * w0.x; acc[i].y += a.x * w0.y; acc[i].z += a.x * w0.z; acc[i].w += a.x * w0.w;
                acc[i].x += a.y * w1.x; acc[i].y += a.y * w1.y; acc[i].z += a.y * w1.z; acc[i].w += a.y * w1.w;
                acc[i].x += a.z * w2.x; acc[i].y += a.z * w2.y; acc[i].z += a.z * w2.z; acc[i].w += a.z * w2.w;
                acc[i].x += a.w * w3.x; acc[i].y += a.w * w3.y; acc[i].z += a.w * w3.z; acc[i].w += a.w * w3.w;
            }
        }
        __syncthreads();
    }

    float4 bb = ((const float4*)bias)[tx];
    #pragma unroll
    for (int i = 0; i < 8; i++) {
        int gr = row0 + ty * 8 + i;
        if (gr < nrows) {
            ((float4*)g_xw)[(size_t)gr * 32 + tx] = acc[i];        // raw for scatter
            float di = g_dinv[gr];
            float nrm = di * di;                                   // self-loop norm
            float4 v;
            v.x = acc[i].x * nrm + bb.x;
            v.y = acc[i].y * nrm + bb.y;
            v.z = acc[i].z * nrm + bb.z;
            v.w = acc[i].w * nrm + bb.w;
            out4[(size_t)gr * 32 + tx] = v;                        // initialized out
        }
    }
}

// ---------------- edge scatter: out[dst] += g_xw[src] * dinv[src]*dinv[dst] ----
// one warp per edge; lane handles one float4 (32 lanes * 4 = 128)
__global__ void k_scatter(const int* __restrict__ src,
                          const int* __restrict__ dst,
                          float* dout, int phase, int e, int n) {
    float* out = phase ? dout : g_h1;
    int warp = (blockIdx.x * blockDim.x + threadIdx.x) >> 5;
    int lane = threadIdx.x & 31;
    if (warp >= e) return;
    int s = src[warp];
    int d = dst[warp];
    if (s < 0 || s >= n || d < 0 || d >= n) return;
    float nrm = g_dinv[s] * g_dinv[d];
    float4 v = ((const float4*)g_xw)[(size_t)s * 32 + lane];
    float* o = out + (size_t)d * HID + lane * 4;
    atomicAdd(o + 0, v.x * nrm);
    atomicAdd(o + 1, v.y * nrm);
    atomicAdd(o + 2, v.z * nrm);
    atomicAdd(o + 3, v.w * nrm);
}

// ---------------- launch -------------------------------------------------------
extern "C" void kernel_launch(void* const* d_in, const int* in_sizes, int n_in,
                              void* d_out, int out_size) {
    // identify inputs by element count (order-agnostic), fallback = dict order
    int i_nf = -1, i_nt = -1, i_ei = -1, i_aw = -1, i_ab = -1;
    int i_w[2] = {-1, -1}, i_b[2] = {-1, -1};
    int nw = 0, nb = 0;
    for (int i = 0; i < n_in; i++) {
        long s = in_sizes[i];
        if      (s == 12800000) i_nf = i;
        else if (s == 100000)   i_nt = i;
        else if (s == 1200000)  i_ei = i;
        else if (s == 65536)    i_aw = i;
        else if (s == 512)      i_ab = i;
        else if (s == 16384)  { if (nw < 2) i_w[nw++] = i; }
        else if (s == 128)    { if (nb < 2) i_b[nb++] = i; }
    }
    if (i_nf < 0) i_nf = 0;
    if (i_nt < 0) i_nt = 1;
    if (i_ei < 0) i_ei = 3;
    if (i_aw < 0) i_aw = 5;
    if (i_ab < 0) i_ab = 6;
    if (i_w[0] < 0) { i_w[0] = 7; i_w[1] = 9; }
    if (i_b[0] < 0) { i_b[0] = 8; i_b[1] = 10; }
    if (i_w[1] < 0) i_w[1] = i_w[0];
    if (i_b[1] < 0) i_b[1] = i_b[0];

    const float* node_feature = (const float*)d_in[i_nf];
    const int*   node_type    = (const int*)d_in[i_nt];
    const int*   edge_index   = (const int*)d_in[i_ei];
    const float* adapt_W      = (const float*)d_in[i_aw];
    const float* adapt_b      = (const float*)d_in[i_ab];
    const float* gcn_W1       = (const float*)d_in[i_w[0]];
    const float* gcn_b1       = (const float*)d_in[i_b[0]];
    const float* gcn_W2       = (const float*)d_in[i_w[1]];
    const float* gcn_b2       = (const float*)d_in[i_b[1]];
    float* out = (float*)d_out;

    int n = in_sizes[i_nt];                 // N = 100000
    if (n > N_NODES) n = N_NODES;           // never overrun scratch
    int e = in_sizes[i_ei] / 2;             // E = 600000
    const int* src = edge_index;
    const int* dst = edge_index + e;

    int tiles = (n + BM - 1) / BM;
    int nb256 = (n + 255) / 256;
    int eb256 = (e + 255) / 256;

    // prep
    k_init<<<nb256, 256>>>(n);
    k_count_types<<<nb256, 256>>>(node_type, n);
    k_deg<<<eb256, 256>>>(dst, e, n);
    k_offsets<<<1, 1>>>();
    k_perm<<<nb256, 256>>>(node_type, n);
    k_dinv<<<nb256, 256>>>(n);

    // adapt: g_res = tanh(x @ W_type + b_type)
    dim3 agrid(tiles, NTYPES);
    k_adapt<<<agrid, GEMM_THREADS>>>(node_feature, adapt_W, adapt_b);

    int sb = ((e + 7) / 8);                         // 8 warps (edges) per 256-thread CTA

    // layer 1: g_xw = g_res @ W1 ; g_h1 = g_xw*dinv^2 + b1 (fused) ; scatter edges
    k_gemm<<<tiles, GEMM_THREADS>>>(0, gcn_W1, gcn_b1, out, n);
    k_scatter<<<sb, 256>>>(src, dst, out, 0, e, n);

    // layer 2: g_xw = g_h1 @ W2 ; out = g_xw*dinv^2 + b2 (fused) ; scatter edges
    k_gemm<<<tiles, GEMM_THREADS>>>(1, gcn_W2, gcn_b2, out, n);
    k_scatter<<<sb, 256>>>(src, dst, out, 1, e, n);
}

// round 15
// speedup vs baseline: 1.3111x; 1.3111x over previous
#include <cuda_runtime.h>
#include <math.h>

#define N_NODES 100000
#define HID 128
#define NTYPES 4
#define BM 64
#define GEMM_THREADS 256

// ---------------- scratch (__device__ globals; referenced ONLY in device code) --
__device__ float g_res[N_NODES * HID];   // adapt output
__device__ float g_xw[N_NODES * HID];    // x @ W scratch (reused both layers)
__device__ float g_h1[N_NODES * HID];    // layer-1 output
__device__ float g_dinv[N_NODES];
__device__ int   g_deg[N_NODES];
__device__ int   g_cnt[NTYPES];
__device__ int   g_off[NTYPES];
__device__ int   g_cur[NTYPES];
__device__ int   g_perm[N_NODES];

// ---------------- prep 1: zero counters, deg=1 (self loop) ---------------------
__global__ void k_init(int n) {
    int i = blockIdx.x * blockDim.x + threadIdx.x;
    if (i < n) g_deg[i] = 1;
    if (i < NTYPES) { g_cnt[i] = 0; g_cur[i] = 0; }
}

// ---------------- prep 2: type histogram + degree (fused; both atomic) ---------
__global__ void k_count_deg(const int* __restrict__ ntype,
                            const int* __restrict__ dst, int n, int e) {
    int i = blockIdx.x * blockDim.x + threadIdx.x;
    if (i < n) {
        int t = ntype[i];
        t = (t < 0) ? 0 : (t >= NTYPES ? NTYPES - 1 : t);
        atomicAdd(&g_cnt[t], 1);
    }
    if (i < e) {
        int d = dst[i];
        if (d >= 0 && d < n) atomicAdd(&g_deg[d], 1);
    }
}

// ---------------- prep 3: type offsets (1 thread) + dinv (fused) ---------------
__global__ void k_off_dinv(int n) {
    int i = blockIdx.x * blockDim.x + threadIdx.x;
    if (i == 0) {
        int acc = 0;
        for (int t = 0; t < NTYPES; t++) { g_off[t] = acc; g_cur[t] = acc; acc += g_cnt[t]; }
    }
    if (i < n) g_dinv[i] = rsqrtf((float)g_deg[i]);
}

// ---------------- prep 4: counting-sort permutation ----------------------------
__global__ void k_perm(const int* __restrict__ ntype, int n) {
    int i = blockIdx.x * blockDim.x + threadIdx.x;
    if (i < n) {
        int t = ntype[i];
        t = (t < 0) ? 0 : (t >= NTYPES ? NTYPES - 1 : t);
        int p = atomicAdd(&g_cur[t], 1);
        if (p >= 0 && p < n) g_perm[p] = i;
    }
}

// ---------------- adapt: per-type gather-GEMM + bias + tanh --------------------
__global__ void __launch_bounds__(GEMM_THREADS)
k_adapt(const float* __restrict__ X,
        const float* __restrict__ aW,
        const float* __restrict__ ab) {
    __shared__ float sW[64 * HID];   // 32KB
    __shared__ float sA[BM * 64];    // 16KB

    int t = blockIdx.y;
    int count = g_cnt[t];
    int row0 = blockIdx.x * BM;
    if (row0 >= count) return;
    int offt = g_off[t];
    int tid = threadIdx.x;
    int tx = tid & 31, ty = tid >> 5;

    float4* sW4 = (float4*)sW;
    float4* sA4 = (float4*)sA;
    const float4* X4 = (const float4*)X;

    float4 acc[8];
    #pragma unroll
    for (int i = 0; i < 8; i++) acc[i] = make_float4(0.f, 0.f, 0.f, 0.f);

    for (int p = 0; p < 2; p++) {
        const float4* W4 = (const float4*)(aW + ((size_t)t * HID + p * 64) * HID);
        for (int i = tid; i < 64 * 32; i += GEMM_THREADS) sW4[i] = W4[i];
        for (int i = tid; i < BM * 16; i += GEMM_THREADS) {
            int r = i >> 4;
            int idx = row0 + r;
            float4 v = make_float4(0.f, 0.f, 0.f, 0.f);
            if (idx < count) {
                int g = g_perm[offt + idx];
                v = X4[(size_t)g * 32 + p * 16 + (i & 15)];
            }
            sA4[i] = v;
        }
        __syncthreads();

        #pragma unroll 4
        for (int k = 0; k < 64; k += 4) {
            float4 w0 = sW4[(k + 0) * 32 + tx];
            float4 w1 = sW4[(k + 1) * 32 + tx];
            float4 w2 = sW4[(k + 2) * 32 + tx];
            float4 w3 = sW4[(k + 3) * 32 + tx];
            #pragma unroll
            for (int i = 0; i < 8; i++) {
                float4 a = sA4[(ty * 8 + i) * 16 + (k >> 2)];
                acc[i].x += a.x * w0.x; acc[i].y += a.x * w0.y; acc[i].z += a.x * w0.z; acc[i].w += a.x * w0.w;
                acc[i].x += a.y * w1.x; acc[i].y += a.y * w1.y; acc[i].z += a.y * w1.z; acc[i].w += a.y * w1.w;
                acc[i].x += a.z * w2.x; acc[i].y += a.z * w2.y; acc[i].z += a.z * w2.z; acc[i].w += a.z * w2.w;
                acc[i].x += a.w * w3.x; acc[i].y += a.w * w3.y; acc[i].z += a.w * w3.z; acc[i].w += a.w * w3.w;
            }
        }
        __syncthreads();
    }

    float4 b = ((const float4*)(ab + t * HID))[tx];
    #pragma unroll
    for (int i = 0; i < 8; i++) {
        int idx = row0 + ty * 8 + i;
        if (idx < count) {
            int g = g_perm[offt + idx];
            float4 v;
            v.x = tanhf(acc[i].x + b.x);
            v.y = tanhf(acc[i].y + b.y);
            v.z = tanhf(acc[i].z + b.z);
            v.w = tanhf(acc[i].w + b.w);
            ((float4*)g_res)[(size_t)g * 32 + tx] = v;
        }
    }
}

// ---------------- dense 128-col GEMM with fused self-loop epilogue --------------
// which = 0: A = g_res, out = g_h1.   which = 1: A = g_h1, out = dout.
__global__ void __launch_bounds__(GEMM_THREADS)
k_gemm(int which, const float* __restrict__ W, const float* __restrict__ bias,
       float* dout, int nrows) {
    __shared__ float sW[64 * HID];   // 32KB
    __shared__ float sA[BM * 64];    // 16KB

    const float4* A4 = which ? (const float4*)g_h1 : (const float4*)g_res;
    float4* out4 = which ? (float4*)dout : (float4*)g_h1;

    int tid = threadIdx.x;
    int row0 = blockIdx.x * BM;
    int tx = tid & 31, ty = tid >> 5;

    float4* sW4 = (float4*)sW;
    float4* sA4 = (float4*)sA;

    float4 acc[8];
    #pragma unroll
    for (int i = 0; i < 8; i++) acc[i] = make_float4(0.f, 0.f, 0.f, 0.f);

    for (int p = 0; p < 2; p++) {
        const float4* W4 = (const float4*)(W + (size_t)p * 64 * HID);
        for (int i = tid; i < 64 * 32; i += GEMM_THREADS) sW4[i] = W4[i];
        for (int i = tid; i < BM * 16; i += GEMM_THREADS) {
            int r = i >> 4;
            int gr = row0 + r;
            sA4[i] = (gr < nrows) ? A4[(size_t)gr * 32 + p * 16 + (i & 15)]
                                  : make_float4(0.f, 0.f, 0.f, 0.f);
        }
        __syncthreads();

        #pragma unroll 4
        for (int k = 0; k < 64; k += 4) {
            float4 w0 = sW4[(k + 0) * 32 + tx];
            float4 w1 = sW4[(k + 1) * 32 + tx];
            float4 w2 = sW4[(k + 2) * 32 + tx];
            float4 w3 = sW4[(k + 3) * 32 + tx];
            #pragma unroll
            for (int i = 0; i < 8; i++) {
                float4 a = sA4[(ty * 8 + i) * 16 + (k >> 2)];
                acc[i].x += a.x * w0.x; acc[i].y += a.x * w0.y; acc[i].z += a.x * w0.z; acc[i].w += a.x * w0.w;
                acc[i].x += a.y * w1.x; acc[i].y += a.y * w1.y; acc[i].z += a.y * w1.z; acc[i].w += a.y * w1.w;
                acc[i].x += a.z * w2.x; acc[i].y += a.z * w2.y; acc[i].z += a.z * w2.z; acc[i].w += a.z * w2.w;
                acc[i].x += a.w * w3.x; acc[i].y += a.w * w3.y; acc[i].z += a.w * w3.z; acc[i].w += a.w * w3.w;
            }
        }
        __syncthreads();
    }

    float4 bb = ((const float4*)bias)[tx];
    #pragma unroll
    for (int i = 0; i < 8; i++) {
        int gr = row0 + ty * 8 + i;
        if (gr < nrows) {
            ((float4*)g_xw)[(size_t)gr * 32 + tx] = acc[i];        // raw for scatter
            float di = g_dinv[gr];
            float nrm = di * di;
            float4 v;
            v.x = acc[i].x * nrm + bb.x;
            v.y = acc[i].y * nrm + bb.y;
            v.z = acc[i].z * nrm + bb.z;
            v.w = acc[i].w * nrm + bb.w;
            out4[(size_t)gr * 32 + tx] = v;                        // self-loop init
        }
    }
}

// ---------------- edge scatter: out[dst] += g_xw[src] * dinv[src]*dinv[dst] ----
// one warp per edge; lane does ONE 128-bit vector atomicAdd (sm_90+ intrinsic)
__global__ void k_scatter(const int* __restrict__ src,
                          const int* __restrict__ dst,
                          float* dout, int phase, int e, int n) {
    float* out = phase ? dout : g_h1;
    int warp = (blockIdx.x * blockDim.x + threadIdx.x) >> 5;
    int lane = threadIdx.x & 31;
    if (warp >= e) return;
    int s = src[warp];
    int d = dst[warp];
    if (s < 0 || s >= n || d < 0 || d >= n) return;
    float nrm = g_dinv[s] * g_dinv[d];
    float4 v = ((const float4*)g_xw)[(size_t)s * 32 + lane];
    v.x *= nrm; v.y *= nrm; v.z *= nrm; v.w *= nrm;
    float4* o = (float4*)(out + (size_t)d * HID + lane * 4);   // 16B-aligned
#if __CUDA_ARCH__ >= 900
    atomicAdd(o, v);                       // single 128-bit RED
#else
    atomicAdd(&o->x, v.x); atomicAdd(&o->y, v.y);
    atomicAdd(&o->z, v.z); atomicAdd(&o->w, v.w);
#endif
}

// ---------------- launch -------------------------------------------------------
extern "C" void kernel_launch(void* const* d_in, const int* in_sizes, int n_in,
                              void* d_out, int out_size) {
    // identify inputs by element count (order-agnostic), fallback = dict order
    int i_nf = -1, i_nt = -1, i_ei = -1, i_aw = -1, i_ab = -1;
    int i_w[2] = {-1, -1}, i_b[2] = {-1, -1};
    int nw = 0, nb = 0;
    for (int i = 0; i < n_in; i++) {
        long s = in_sizes[i];
        if      (s == 12800000) i_nf = i;
        else if (s == 100000)   i_nt = i;
        else if (s == 1200000)  i_ei = i;
        else if (s == 65536)    i_aw = i;
        else if (s == 512)      i_ab = i;
        else if (s == 16384)  { if (nw < 2) i_w[nw++] = i; }
        else if (s == 128)    { if (nb < 2) i_b[nb++] = i; }
    }
    if (i_nf < 0) i_nf = 0;
    if (i_nt < 0) i_nt = 1;
    if (i_ei < 0) i_ei = 3;
    if (i_aw < 0) i_aw = 5;
    if (i_ab < 0) i_ab = 6;
    if (i_w[0] < 0) { i_w[0] = 7; i_w[1] = 9; }
    if (i_b[0] < 0) { i_b[0] = 8; i_b[1] = 10; }
    if (i_w[1] < 0) i_w[1] = i_w[0];
    if (i_b[1] < 0) i_b[1] = i_b[0];

    const float* node_feature = (const float*)d_in[i_nf];
    const int*   node_type    = (const int*)d_in[i_nt];
    const int*   edge_index   = (const int*)d_in[i_ei];
    const float* adapt_W      = (const float*)d_in[i_aw];
    const float* adapt_b      = (const float*)d_in[i_ab];
    const float* gcn_W1       = (const float*)d_in[i_w[0]];
    const float* gcn_b1       = (const float*)d_in[i_b[0]];
    const float* gcn_W2       = (const float*)d_in[i_w[1]];
    const float* gcn_b2       = (const float*)d_in[i_b[1]];
    float* out = (float*)d_out;

    int n = in_sizes[i_nt];
    if (n > N_NODES) n = N_NODES;
    int e = in_sizes[i_ei] / 2;
    const int* src = edge_index;
    const int* dst = edge_index + e;

    int tiles = (n + BM - 1) / BM;
    int nb256 = (n + 255) / 256;
    int eb256 = (e + 255) / 256;

    // prep (4 launches)
    k_init<<<nb256, 256>>>(n);
    k_count_deg<<<eb256, 256>>>(node_type, dst, n, e);
    k_off_dinv<<<nb256, 256>>>(n);
    k_perm<<<nb256, 256>>>(node_type, n);

    // adapt (launch #5): g_res = tanh(x @ W_type + b_type)
    dim3 agrid(tiles, NTYPES);
    k_adapt<<<agrid, GEMM_THREADS>>>(node_feature, adapt_W, adapt_b);

    int sb = ((e + 7) / 8);

    // layer 1 (launches #6,#7): gemm(+fused self-loop) then edge scatter
    k_gemm<<<tiles, GEMM_THREADS>>>(0, gcn_W1, gcn_b1, out, n);
    k_scatter<<<sb, 256>>>(src, dst, out, 0, e, n);

    // layer 2 (launches #8,#9)
    k_gemm<<<tiles, GEMM_THREADS>>>(1, gcn_W2, gcn_b2, out, n);
    k_scatter<<<sb, 256>>>(src, dst, out, 1, e, n);
}

// round 16
// speedup vs baseline: 1.4246x; 1.0865x over previous
#include <cuda_runtime.h>
#include <math.h>

#define N_NODES 100000
#define HID 128
#define NTYPES 4
#define BM 64
#define GEMM_THREADS 256

// ---------------- scratch (__device__ globals; referenced ONLY in device code) --
__device__ float g_res[N_NODES * HID];   // adapt output
__device__ float g_xw[N_NODES * HID];    // x @ W scratch (reused both layers)
__device__ float g_h1[N_NODES * HID];    // layer-1 output
__device__ float g_dinv[N_NODES];
__device__ int   g_deg[N_NODES];
__device__ int   g_cnt[NTYPES];
__device__ int   g_off[NTYPES];
__device__ int   g_cur[NTYPES];
__device__ int   g_perm[N_NODES];

// ---------------- prep 1: zero counters, deg=1 (self loop) ---------------------
__global__ void k_init(int n) {
    int i = blockIdx.x * blockDim.x + threadIdx.x;
    if (i < n) g_deg[i] = 1;
    if (i < NTYPES) { g_cnt[i] = 0; g_cur[i] = 0; }
}

// ---------------- prep 2: type histogram (smem-aggregated) + degree ------------
__global__ void k_count_deg(const int* __restrict__ ntype,
                            const int* __restrict__ dst, int n, int e) {
    __shared__ int h[NTYPES];
    int tid = threadIdx.x;
    if (tid < NTYPES) h[tid] = 0;
    __syncthreads();
    int i = blockIdx.x * blockDim.x + tid;
    if (i < n) {
        int t = ntype[i];
        t = (t < 0) ? 0 : (t >= NTYPES ? NTYPES - 1 : t);
        atomicAdd(&h[t], 1);                       // block-local (smem)
    }
    if (i < e) {
        int d = dst[i];
        if (d >= 0 && d < n) atomicAdd(&g_deg[d], 1);   // spread addresses, cheap
    }
    __syncthreads();
    if (tid < NTYPES && h[tid] > 0) atomicAdd(&g_cnt[tid], h[tid]);  // 4/block
}

// ---------------- prep 3: type offsets (1 thread) + dinv (fused) ---------------
__global__ void k_off_dinv(int n) {
    int i = blockIdx.x * blockDim.x + threadIdx.x;
    if (i == 0) {
        int acc = 0;
        for (int t = 0; t < NTYPES; t++) { g_off[t] = acc; g_cur[t] = acc; acc += g_cnt[t]; }
    }
    if (i < n) g_dinv[i] = rsqrtf((float)g_deg[i]);
}

// ---------------- prep 4: counting-sort permutation (smem-aggregated) ----------
__global__ void k_perm(const int* __restrict__ ntype, int n) {
    __shared__ int h[NTYPES];      // counts, then local cursors
    __shared__ int base[NTYPES];   // block base in global order
    int tid = threadIdx.x;
    if (tid < NTYPES) h[tid] = 0;
    __syncthreads();
    int i = blockIdx.x * blockDim.x + tid;
    int t = -1;
    if (i < n) {
        t = ntype[i];
        t = (t < 0) ? 0 : (t >= NTYPES ? NTYPES - 1 : t);
        atomicAdd(&h[t], 1);                        // block-local count
    }
    __syncthreads();
    if (tid < NTYPES) {
        int c = h[tid];
        base[tid] = (c > 0) ? atomicAdd(&g_cur[tid], c) : 0;   // 1 global atomic/type
        h[tid] = 0;                                 // reset as local cursor
    }
    __syncthreads();
    if (i < n) {
        int p = base[t] + atomicAdd(&h[t], 1);      // local offset (smem)
        g_perm[p] = i;
    }
}

// ---------------- adapt: per-type gather-GEMM + bias + tanh --------------------
__global__ void __launch_bounds__(GEMM_THREADS)
k_adapt(const float* __restrict__ X,
        const float* __restrict__ aW,
        const float* __restrict__ ab) {
    __shared__ float sW[64 * HID];   // 32KB
    __shared__ float sA[BM * 64];    // 16KB

    int t = blockIdx.y;
    int count = g_cnt[t];
    int row0 = blockIdx.x * BM;
    if (row0 >= count) return;
    int offt = g_off[t];
    int tid = threadIdx.x;
    int tx = tid & 31, ty = tid >> 5;

    float4* sW4 = (float4*)sW;
    float4* sA4 = (float4*)sA;
    const float4* X4 = (const float4*)X;

    float4 acc[8];
    #pragma unroll
    for (int i = 0; i < 8; i++) acc[i] = make_float4(0.f, 0.f, 0.f, 0.f);

    for (int p = 0; p < 2; p++) {
        const float4* W4 = (const float4*)(aW + ((size_t)t * HID + p * 64) * HID);
        for (int i = tid; i < 64 * 32; i += GEMM_THREADS) sW4[i] = W4[i];
        for (int i = tid; i < BM * 16; i += GEMM_THREADS) {
            int r = i >> 4;
            int idx = row0 + r;
            float4 v = make_float4(0.f, 0.f, 0.f, 0.f);
            if (idx < count) {
                int g = g_perm[offt + idx];
                v = X4[(size_t)g * 32 + p * 16 + (i & 15)];
            }
            sA4[i] = v;
        }
        __syncthreads();

        #pragma unroll 4
        for (int k = 0; k < 64; k += 4) {
            float4 w0 = sW4[(k + 0) * 32 + tx];
            float4 w1 = sW4[(k + 1) * 32 + tx];
            float4 w2 = sW4[(k + 2) * 32 + tx];
            float4 w3 = sW4[(k + 3) * 32 + tx];
            #pragma unroll
            for (int i = 0; i < 8; i++) {
                float4 a = sA4[(ty * 8 + i) * 16 + (k >> 2)];
                acc[i].x += a.x * w0.x; acc[i].y += a.x * w0.y; acc[i].z += a.x * w0.z; acc[i].w += a.x * w0.w;
                acc[i].x += a.y * w1.x; acc[i].y += a.y * w1.y; acc[i].z += a.y * w1.z; acc[i].w += a.y * w1.w;
                acc[i].x += a.z * w2.x; acc[i].y += a.z * w2.y; acc[i].z += a.z * w2.z; acc[i].w += a.z * w2.w;
                acc[i].x += a.w * w3.x; acc[i].y += a.w * w3.y; acc[i].z += a.w * w3.z; acc[i].w += a.w * w3.w;
            }
        }
        __syncthreads();
    }

    float4 b = ((const float4*)(ab + t * HID))[tx];
    #pragma unroll
    for (int i = 0; i < 8; i++) {
        int idx = row0 + ty * 8 + i;
        if (idx < count) {
            int g = g_perm[offt + idx];
            float4 v;
            v.x = tanhf(acc[i].x + b.x);
            v.y = tanhf(acc[i].y + b.y);
            v.z = tanhf(acc[i].z + b.z);
            v.w = tanhf(acc[i].w + b.w);
            ((float4*)g_res)[(size_t)g * 32 + tx] = v;
        }
    }
}

// ---------------- dense 128-col GEMM with fused self-loop epilogue --------------
// which = 0: A = g_res, out = g_h1.   which = 1: A = g_h1, out = dout.
__global__ void __launch_bounds__(GEMM_THREADS)
k_gemm(int which, const float* __restrict__ W, const float* __restrict__ bias,
       float* dout, int nrows) {
    __shared__ float sW[64 * HID];   // 32KB
    __shared__ float sA[BM * 64];    // 16KB

    const float4* A4 = which ? (const float4*)g_h1 : (const float4*)g_res;
    float4* out4 = which ? (float4*)dout : (float4*)g_h1;

    int tid = threadIdx.x;
    int row0 = blockIdx.x * BM;
    int tx = tid & 31, ty = tid >> 5;

    float4* sW4 = (float4*)sW;
    float4* sA4 = (float4*)sA;

    float4 acc[8];
    #pragma unroll
    for (int i = 0; i < 8; i++) acc[i] = make_float4(0.f, 0.f, 0.f, 0.f);

    for (int p = 0; p < 2; p++) {
        const float4* W4 = (const float4*)(W + (size_t)p * 64 * HID);
        for (int i = tid; i < 64 * 32; i += GEMM_THREADS) sW4[i] = W4[i];
        for (int i = tid; i < BM * 16; i += GEMM_THREADS) {
            int r = i >> 4;
            int gr = row0 + r;
            sA4[i] = (gr < nrows) ? A4[(size_t)gr * 32 + p * 16 + (i & 15)]
                                  : make_float4(0.f, 0.f, 0.f, 0.f);
        }
        __syncthreads();

        #pragma unroll 4
        for (int k = 0; k < 64; k += 4) {
            float4 w0 = sW4[(k + 0) * 32 + tx];
            float4 w1 = sW4[(k + 1) * 32 + tx];
            float4 w2 = sW4[(k + 2) * 32 + tx];
            float4 w3 = sW4[(k + 3) * 32 + tx];
            #pragma unroll
            for (int i = 0; i < 8; i++) {
                float4 a = sA4[(ty * 8 + i) * 16 + (k >> 2)];
                acc[i].x += a.x * w0.x; acc[i].y += a.x * w0.y; acc[i].z += a.x * w0.z; acc[i].w += a.x * w0.w;
                acc[i].x += a.y * w1.x; acc[i].y += a.y * w1.y; acc[i].z += a.y * w1.z; acc[i].w += a.y * w1.w;
                acc[i].x += a.z * w2.x; acc[i].y += a.z * w2.y; acc[i].z += a.z * w2.z; acc[i].w += a.z * w2.w;
                acc[i].x += a.w * w3.x; acc[i].y += a.w * w3.y; acc[i].z += a.w * w3.z; acc[i].w += a.w * w3.w;
            }
        }
        __syncthreads();
    }

    float4 bb = ((const float4*)bias)[tx];
    #pragma unroll
    for (int i = 0; i < 8; i++) {
        int gr = row0 + ty * 8 + i;
        if (gr < nrows) {
            ((float4*)g_xw)[(size_t)gr * 32 + tx] = acc[i];        // raw for scatter
            float di = g_dinv[gr];
            float nrm = di * di;
            float4 v;
            v.x = acc[i].x * nrm + bb.x;
            v.y = acc[i].y * nrm + bb.y;
            v.z = acc[i].z * nrm + bb.z;
            v.w = acc[i].w * nrm + bb.w;
            out4[(size_t)gr * 32 + tx] = v;                        // self-loop init
        }
    }
}

// ---------------- edge scatter: out[dst] += g_xw[src] * dinv[src]*dinv[dst] ----
// one warp per edge; lane does ONE 128-bit vector atomicAdd (sm_90+ intrinsic)
__global__ void k_scatter(const int* __restrict__ src,
                          const int* __restrict__ dst,
                          float* dout, int phase, int e, int n) {
    float* out = phase ? dout : g_h1;
    int warp = (blockIdx.x * blockDim.x + threadIdx.x) >> 5;
    int lane = threadIdx.x & 31;
    if (warp >= e) return;
    int s = src[warp];
    int d = dst[warp];
    if (s < 0 || s >= n || d < 0 || d >= n) return;
    float nrm = g_dinv[s] * g_dinv[d];
    float4 v = ((const float4*)g_xw)[(size_t)s * 32 + lane];
    v.x *= nrm; v.y *= nrm; v.z *= nrm; v.w *= nrm;
    float4* o = (float4*)(out + (size_t)d * HID + lane * 4);   // 16B-aligned
#if __CUDA_ARCH__ >= 900
    atomicAdd(o, v);                       // single 128-bit RED
#else
    atomicAdd(&o->x, v.x); atomicAdd(&o->y, v.y);
    atomicAdd(&o->z, v.z); atomicAdd(&o->w, v.w);
#endif
}

// ---------------- launch -------------------------------------------------------
extern "C" void kernel_launch(void* const* d_in, const int* in_sizes, int n_in,
                              void* d_out, int out_size) {
    // identify inputs by element count (order-agnostic), fallback = dict order
    int i_nf = -1, i_nt = -1, i_ei = -1, i_aw = -1, i_ab = -1;
    int i_w[2] = {-1, -1}, i_b[2] = {-1, -1};
    int nw = 0, nb = 0;
    for (int i = 0; i < n_in; i++) {
        long s = in_sizes[i];
        if      (s == 12800000) i_nf = i;
        else if (s == 100000)   i_nt = i;
        else if (s == 1200000)  i_ei = i;
        else if (s == 65536)    i_aw = i;
        else if (s == 512)      i_ab = i;
        else if (s == 16384)  { if (nw < 2) i_w[nw++] = i; }
        else if (s == 128)    { if (nb < 2) i_b[nb++] = i; }
    }
    if (i_nf < 0) i_nf = 0;
    if (i_nt < 0) i_nt = 1;
    if (i_ei < 0) i_ei = 3;
    if (i_aw < 0) i_aw = 5;
    if (i_ab < 0) i_ab = 6;
    if (i_w[0] < 0) { i_w[0] = 7; i_w[1] = 9; }
    if (i_b[0] < 0) { i_b[0] = 8; i_b[1] = 10; }
    if (i_w[1] < 0) i_w[1] = i_w[0];
    if (i_b[1] < 0) i_b[1] = i_b[0];

    const float* node_feature = (const float*)d_in[i_nf];
    const int*   node_type    = (const int*)d_in[i_nt];
    const int*   edge_index   = (const int*)d_in[i_ei];
    const float* adapt_W      = (const float*)d_in[i_aw];
    const float* adapt_b      = (const float*)d_in[i_ab];
    const float* gcn_W1       = (const float*)d_in[i_w[0]];
    const float* gcn_b1       = (const float*)d_in[i_b[0]];
    const float* gcn_W2       = (const float*)d_in[i_w[1]];
    const float* gcn_b2       = (const float*)d_in[i_b[1]];
    float* out = (float*)d_out;

    int n = in_sizes[i_nt];
    if (n > N_NODES) n = N_NODES;
    int e = in_sizes[i_ei] / 2;
    const int* src = edge_index;
    const int* dst = edge_index + e;

    int tiles = (n + BM - 1) / BM;
    int nb256 = (n + 255) / 256;
    int eb256 = (e + 255) / 256;

    // prep (4 launches)
    k_init<<<nb256, 256>>>(n);
    k_count_deg<<<eb256, 256>>>(node_type, dst, n, e);
    k_off_dinv<<<nb256, 256>>>(n);
    k_perm<<<nb256, 256>>>(node_type, n);

    // adapt (launch #5): g_res = tanh(x @ W_type + b_type)
    dim3 agrid(tiles, NTYPES);
    k_adapt<<<agrid, GEMM_THREADS>>>(node_feature, adapt_W, adapt_b);

    int sb = ((e + 7) / 8);

    // layer 1 (launches #6,#7): gemm(+fused self-loop) then edge scatter
    k_gemm<<<tiles, GEMM_THREADS>>>(0, gcn_W1, gcn_b1, out, n);
    k_scatter<<<sb, 256>>>(src, dst, out, 0, e, n);

    // layer 2 (launches #8,#9)
    k_gemm<<<tiles, GEMM_THREADS>>>(1, gcn_W2, gcn_b2, out, n);
    k_scatter<<<sb, 256>>>(src, dst, out, 1, e, n);
}